// round 2
// baseline (speedup 1.0000x reference)
#include <cuda_runtime.h>
#include <math.h>

// ---------------- problem constants ----------------
#define BB   4
#define LL   1024
#define DM   512        // d_model
#define DI   1024       // d_inner
#define DS   64         // d_state
#define NH   16         // heads
#define HD   64         // headdim
#define CD   1152       // conv dim = DI + 2*DS
#define DIP  2192       // in_proj out = 2*DI + 2*DS + NH
#define MM   (BB*LL)    // 4096 tokens

// ---------------- scratch (static device memory; no allocs) ----------------
__device__ __align__(128) float g_h   [MM*DM];        //  8.4 MB  normed input
__device__ __align__(128) float g_zx  [2][MM*DIP];    // 71.8 MB  in_proj out per dir
__device__ __align__(128) float g_conv[2][MM*CD];     // 37.7 MB  silu(conv) per dir
__device__ __align__(128) float g_dt  [2][MM*NH];     //  0.5 MB
__device__ __align__(128) float g_dec [2][MM*NH];     //  0.5 MB
__device__ __align__(128) float g_y   [2][MM*DI];     // 33.6 MB  scan out -> gated/normed
__device__ __align__(128) float g_cat [MM*2*DM];      // 16.8 MB  [fo | bo]

// ---------------- helpers ----------------
__device__ __forceinline__ float block_reduce_sum_256(float v, float* red) {
    int tid = threadIdx.x;
    #pragma unroll
    for (int o = 16; o; o >>= 1) v += __shfl_xor_sync(0xffffffffu, v, o);
    if ((tid & 31) == 0) red[tid >> 5] = v;
    __syncthreads();
    float t = (tid < 8) ? red[tid] : 0.f;
    if (tid < 32) {
        #pragma unroll
        for (int o = 4; o; o >>= 1) t += __shfl_xor_sync(0xffffffffu, t, o);
        if (tid == 0) red[0] = t;
    }
    __syncthreads();
    return red[0];
}

// ---------------- K1: input rmsnorm ----------------
__global__ void k_rmsnorm_in(const float* __restrict__ x, const float* __restrict__ w) {
    int row = blockIdx.x;
    int tid = threadIdx.x;
    const float* xr = x + (size_t)row * DM;
    float v0 = xr[tid], v1 = xr[tid + 256];
    __shared__ float red[8];
    float ss = block_reduce_sum_256(v0 * v0 + v1 * v1, red);
    float scale = rsqrtf(ss / (float)DM + 1e-5f);
    g_h[(size_t)row * DM + tid]       = v0 * scale * w[tid];
    g_h[(size_t)row * DM + tid + 256] = v1 * scale * w[tid + 256];
}

// ---------------- K2: generic fp32 NT GEMM: C[M,N] = A[M,K] @ B[N,K]^T (+R) -------
// grid: (ceil(N/128), M/128), block 256 threads, each computes 8x8.
#define GBM 128
#define GBN 128
#define GBK 8
__global__ void __launch_bounds__(256, 2) k_gemm_nt(
    const float* __restrict__ A, const float* __restrict__ Bw,
    float* __restrict__ C, const float* __restrict__ R,
    int N, int K, int ldc)
{
    __shared__ __align__(16) float As[GBK][GBM];
    __shared__ __align__(16) float Bs[GBK][GBN];

    int tid = threadIdx.x;
    int m0 = blockIdx.y * GBM;
    int n0 = blockIdx.x * GBN;
    int ty = tid >> 4;       // 0..15
    int tx = tid & 15;       // 0..15

    int lrow = tid >> 1;           // 0..127
    int lk4  = (tid & 1) * 4;      // 0 or 4

    float acc[8][8];
    #pragma unroll
    for (int i = 0; i < 8; i++)
        #pragma unroll
        for (int j = 0; j < 8; j++) acc[i][j] = 0.f;

    int nk = K / GBK;
    for (int kt = 0; kt < nk; kt++) {
        if (kt) __syncthreads();
        int k0 = kt * GBK;
        // A tile (M rows always valid: M multiple of 128)
        float4 a = *(const float4*)&A[(size_t)(m0 + lrow) * K + k0 + lk4];
        As[lk4 + 0][lrow] = a.x; As[lk4 + 1][lrow] = a.y;
        As[lk4 + 2][lrow] = a.z; As[lk4 + 3][lrow] = a.w;
        // B tile (guard partial N)
        float4 b4;
        if (n0 + lrow < N) b4 = *(const float4*)&Bw[(size_t)(n0 + lrow) * K + k0 + lk4];
        else               b4 = make_float4(0.f, 0.f, 0.f, 0.f);
        Bs[lk4 + 0][lrow] = b4.x; Bs[lk4 + 1][lrow] = b4.y;
        Bs[lk4 + 2][lrow] = b4.z; Bs[lk4 + 3][lrow] = b4.w;
        __syncthreads();

        #pragma unroll
        for (int k = 0; k < GBK; k++) {
            float4 am0 = *(const float4*)&As[k][ty * 8];
            float4 am1 = *(const float4*)&As[k][ty * 8 + 4];
            float4 bn0 = *(const float4*)&Bs[k][tx * 8];
            float4 bn1 = *(const float4*)&Bs[k][tx * 8 + 4];
            float am[8] = {am0.x, am0.y, am0.z, am0.w, am1.x, am1.y, am1.z, am1.w};
            float bn[8] = {bn0.x, bn0.y, bn0.z, bn0.w, bn1.x, bn1.y, bn1.z, bn1.w};
            #pragma unroll
            for (int i = 0; i < 8; i++)
                #pragma unroll
                for (int j = 0; j < 8; j++)
                    acc[i][j] = fmaf(am[i], bn[j], acc[i][j]);
        }
    }

    #pragma unroll
    for (int i = 0; i < 8; i++) {
        int gm = m0 + ty * 8 + i;
        #pragma unroll
        for (int j = 0; j < 8; j++) {
            int gn = n0 + tx * 8 + j;
            if (gn < N) {
                float v = acc[i][j];
                if (R) v += R[(size_t)gm * ldc + gn];
                C[(size_t)gm * ldc + gn] = v;
            }
        }
    }
}

// ---------------- K3: conv1d + silu + softplus(dt) + decay ----------------
__global__ void k_conv(int dir,
                       const float* __restrict__ conv_w, const float* __restrict__ conv_b,
                       const float* __restrict__ dt_bias, const float* __restrict__ A_log)
{
    int token = blockIdx.x;           // b*L + s
    int b = token >> 10, s = token & 1023;
    const float* zx = g_zx[dir];
    float* out = g_conv[dir] + (size_t)token * CD;

    for (int c = threadIdx.x; c < CD; c += blockDim.x) {
        float acc = conv_b[c];
        const float* w = conv_w + c * 4;
        #pragma unroll
        for (int k = 0; k < 4; k++) {
            int sp = (dir == 0) ? (s - 3 + k) : (s + 3 - k);
            if (sp >= 0 && sp < LL)
                acc = fmaf(zx[(size_t)(b * LL + sp) * DIP + DI + c], w[k], acc);
        }
        out[c] = acc / (1.f + __expf(-acc));   // silu
    }
    if (threadIdx.x < NH) {
        int h = threadIdx.x;
        float v = zx[(size_t)token * DIP + DI + CD + h] + dt_bias[h];
        float dt = (v > 20.f) ? v : log1pf(expf(v));      // softplus
        g_dt[dir][token * NH + h]  = dt;
        g_dec[dir][token * NH + h] = expf(-dt * expf(A_log[h]));
    }
}

// ---------------- K4: selective scan ----------------
// block = (dir, b, h). 256 threads: thread owns p = tid>>2 (0..63), n-slice of 16.
__global__ void __launch_bounds__(256, 1) k_scan(const float* __restrict__ fD,
                                                 const float* __restrict__ bD)
{
    int blk = blockIdx.x;
    int dir = blk >> 6;
    int b   = (blk >> 4) & 3;
    int h   = blk & 15;
    const float* conv = g_conv[dir];
    const float* dts  = g_dt[dir];
    const float* decs = g_dec[dir];
    float* y = g_y[dir];
    float Dh = (dir ? bD : fD)[h];

    int tid = threadIdx.x;
    int p  = tid >> 2;
    int nb = (tid & 3) * 16;

    float st[16];
    #pragma unroll
    for (int j = 0; j < 16; j++) st[j] = 0.f;

    __shared__ float sm[194];  // [x 0..63 | B 64..127 | C 128..191 | dec | dt]

    for (int t = 0; t < LL; t++) {
        int s = dir ? (LL - 1 - t) : t;
        int token = b * LL + s;
        __syncthreads();
        if (tid < 192) {
            int c = (tid < 64) ? (h * 64 + tid)
                  : (tid < 128) ? (DI + (tid - 64))
                                : (DI + 64 + (tid - 128));
            sm[tid] = conv[(size_t)token * CD + c];
        } else if (tid == 192) sm[192] = decs[token * NH + h];
        else if (tid == 193)   sm[193] = dts[token * NH + h];
        __syncthreads();

        float dec = sm[192];
        float dtx = sm[193] * sm[p];
        float acc = 0.f;
        #pragma unroll
        for (int j = 0; j < 16; j++) {
            float Bv = sm[64 + nb + j];
            float Cv = sm[128 + nb + j];
            st[j] = fmaf(st[j], dec, dtx * Bv);
            acc = fmaf(st[j], Cv, acc);
        }
        acc += __shfl_xor_sync(0xffffffffu, acc, 1);
        acc += __shfl_xor_sync(0xffffffffu, acc, 2);
        if ((tid & 3) == 0)
            y[(size_t)token * DI + h * 64 + p] = acc + Dh * sm[p];
    }
}

// ---------------- K5: gating (y * silu(z)) + rmsnorm ----------------
__global__ void k_gatenorm(const float* __restrict__ f_gw, const float* __restrict__ b_gw)
{
    int row = blockIdx.x;
    int dir = blockIdx.y;
    const float* gw = dir ? b_gw : f_gw;
    const float* z = g_zx[dir] + (size_t)row * DIP;   // z = first DI cols
    float* y = g_y[dir] + (size_t)row * DI;
    int tid = threadIdx.x;

    float g[4];
    float ss = 0.f;
    #pragma unroll
    for (int i = 0; i < 4; i++) {
        int c = tid + i * 256;
        float zv = z[c];
        float gv = y[c] * (zv / (1.f + __expf(-zv)));
        g[i] = gv;
        ss += gv * gv;
    }
    __shared__ float red[8];
    float tot = block_reduce_sum_256(ss, red);
    float scale = rsqrtf(tot / (float)DI + 1e-5f);
    #pragma unroll
    for (int i = 0; i < 4; i++) {
        int c = tid + i * 256;
        y[c] = g[i] * scale * gw[c];
    }
}

// ---------------- launcher ----------------
extern "C" void kernel_launch(void* const* d_in, const int* in_sizes, int n_in,
                              void* d_out, int out_size)
{
    (void)in_sizes; (void)n_in; (void)out_size;
    const float* x       = (const float*)d_in[0];
    const float* norm_w  = (const float*)d_in[1];
    const float* in_w[2]   = {(const float*)d_in[2],  (const float*)d_in[10]};
    const float* conv_w[2] = {(const float*)d_in[3],  (const float*)d_in[11]};
    const float* conv_b[2] = {(const float*)d_in[4],  (const float*)d_in[12]};
    const float* dt_b[2]   = {(const float*)d_in[5],  (const float*)d_in[13]};
    const float* A_log[2]  = {(const float*)d_in[6],  (const float*)d_in[14]};
    const float* Dp[2]     = {(const float*)d_in[7],  (const float*)d_in[15]};
    const float* gnorm[2]  = {(const float*)d_in[8],  (const float*)d_in[16]};
    const float* out_w[2]  = {(const float*)d_in[9],  (const float*)d_in[17]};
    const float* proj_w    = (const float*)d_in[18];
    float* out = (float*)d_out;

    float *p_h, *p_zx, *p_y, *p_cat;
    cudaGetSymbolAddress((void**)&p_h,   g_h);
    cudaGetSymbolAddress((void**)&p_zx,  g_zx);
    cudaGetSymbolAddress((void**)&p_y,   g_y);
    cudaGetSymbolAddress((void**)&p_cat, g_cat);

    // 1. input rmsnorm
    k_rmsnorm_in<<<MM, 256>>>(x, norm_w);

    // 2. in_proj (both dirs): zx[dir] = h @ in_w[dir]^T   (4096 x 2192, K=512)
    {
        dim3 grid((DIP + GBN - 1) / GBN, MM / GBM);
        for (int d = 0; d < 2; d++)
            k_gemm_nt<<<grid, 256>>>(p_h, in_w[d],
                                     p_zx + (size_t)d * MM * DIP, nullptr,
                                     DIP, DM, DIP);
    }

    // 3. conv + activations
    for (int d = 0; d < 2; d++)
        k_conv<<<MM, 256>>>(d, conv_w[d], conv_b[d], dt_b[d], A_log[d]);

    // 4. selective scan (both dirs in one launch)
    k_scan<<<128, 256>>>(Dp[0], Dp[1]);

    // 5. gate + rmsnorm
    {
        dim3 grid(MM, 2);
        k_gatenorm<<<grid, 256>>>(gnorm[0], gnorm[1]);
    }

    // 6. out_proj: cat[:, dir*512:+512] = y[dir] @ out_w[dir]^T  (4096 x 512, K=1024)
    {
        dim3 grid((DM + GBN - 1) / GBN, MM / GBM);
        for (int d = 0; d < 2; d++)
            k_gemm_nt<<<grid, 256>>>(p_y + (size_t)d * MM * DI, out_w[d],
                                     p_cat + (size_t)d * DM, nullptr,
                                     DM, DI, 2 * DM);
    }

    // 7. final: out = x + cat @ proj_w^T  (4096 x 512, K=1024)
    {
        dim3 grid((DM + GBN - 1) / GBN, MM / GBM);
        k_gemm_nt<<<grid, 256>>>(p_cat, proj_w, out, x, DM, 2 * DM, DM);
    }
}

// round 3
// speedup vs baseline: 2.5071x; 2.5071x over previous
#include <cuda_runtime.h>
#include <math.h>
#include <stdint.h>

// ---------------- problem constants ----------------
#define BB   4
#define LL   1024
#define DM   512        // d_model
#define DI   1024       // d_inner
#define DS   64         // d_state
#define NH   16         // heads
#define HD   64         // headdim
#define CD   1152       // conv dim = DI + 2*DS
#define DIP  2192       // in_proj out = 2*DI + 2*DS + NH
#define MM   (BB*LL)    // 4096 tokens

// ---------------- scratch (static device memory; no allocs) ----------------
__device__ __align__(128) float g_h   [MM*DM];
__device__ __align__(128) float g_zx  [2][MM*DIP];
__device__ __align__(128) float g_conv[2][MM*CD];
__device__ __align__(128) float g_dt  [2][MM*NH];
__device__ __align__(128) float g_dec [2][MM*NH];
__device__ __align__(128) float g_y   [2][MM*DI];
__device__ __align__(128) float g_cat [MM*2*DM];

// ---------------- helpers ----------------
__device__ __forceinline__ float block_reduce_sum_256(float v, float* red) {
    int tid = threadIdx.x;
    #pragma unroll
    for (int o = 16; o; o >>= 1) v += __shfl_xor_sync(0xffffffffu, v, o);
    if ((tid & 31) == 0) red[tid >> 5] = v;
    __syncthreads();
    float t = (tid < 8) ? red[tid] : 0.f;
    if (tid < 32) {
        #pragma unroll
        for (int o = 4; o; o >>= 1) t += __shfl_xor_sync(0xffffffffu, t, o);
        if (tid == 0) red[0] = t;
    }
    __syncthreads();
    return red[0];
}

__device__ __forceinline__ uint32_t f2tf32(float f) {
    uint32_t u;
    asm("cvt.rna.tf32.f32 %0, %1;" : "=r"(u) : "f"(f));
    return u;
}

// ---------------- K1: input rmsnorm ----------------
__global__ void k_rmsnorm_in(const float* __restrict__ x, const float* __restrict__ w) {
    int row = blockIdx.x;
    int tid = threadIdx.x;
    const float* xr = x + (size_t)row * DM;
    float v0 = xr[tid], v1 = xr[tid + 256];
    __shared__ float red[8];
    float ss = block_reduce_sum_256(v0 * v0 + v1 * v1, red);
    float scale = rsqrtf(ss / (float)DM + 1e-5f);
    g_h[(size_t)row * DM + tid]       = v0 * scale * w[tid];
    g_h[(size_t)row * DM + tid + 256] = v1 * scale * w[tid + 256];
}

// ---------------- K2: tf32 tensor-core NT GEMM ----------------
// C[M,N] = A[M,K] @ B[N,K]^T (+R).  Block tile 128x128, K-tile 32.
// 8 warps, each computes 64(m) x 32(n) via m16n8k8 tf32 mma.sync.
// SMEM rows padded to 36 u32 -> fragment LDS conflict-free.
#define GKT   32
#define GPAD  36
#define TILEW (128*GPAD)          // u32 per (matrix, buffer)
#define GEMM_SMEM (4*TILEW*4)     // bytes: A0,A1,B0,B1

__global__ void __launch_bounds__(256) k_gemm_tf32(
    const float* __restrict__ A, const float* __restrict__ Bw,
    float* __restrict__ C, const float* __restrict__ R,
    int N, int K, int ldc)
{
    extern __shared__ uint32_t smem[];
    uint32_t* Abuf[2] = { smem,            smem + TILEW };
    uint32_t* Bbuf[2] = { smem + 2*TILEW,  smem + 3*TILEW };

    int tid  = threadIdx.x;
    int warp = tid >> 5, lane = tid & 31;
    int grp  = lane >> 2, tig = lane & 3;
    int m0 = blockIdx.y * 128;
    int n0 = blockIdx.x * 128;
    int mb  = (warp & 1) * 64;     // warp m-offset
    int nb2 = (warp >> 1) * 32;    // warp n-offset

    float c[4][4][4];
    #pragma unroll
    for (int mi = 0; mi < 4; mi++)
        #pragma unroll
        for (int ni = 0; ni < 4; ni++)
            #pragma unroll
            for (int q = 0; q < 4; q++) c[mi][ni][q] = 0.f;

    float4 av[4], bv[4];

    // --- stage tile kt into registers ---
    auto load_regs = [&](int kt) {
        int kc = kt * GKT;
        #pragma unroll
        for (int i = 0; i < 4; i++) {
            int idx = tid + i * 256;
            int row = idx >> 3, kq = idx & 7;
            av[i] = *(const float4*)&A[(size_t)(m0 + row) * K + kc + kq * 4];
        }
        #pragma unroll
        for (int i = 0; i < 4; i++) {
            int idx = tid + i * 256;
            int row = idx >> 3, kq = idx & 7;
            if (n0 + row < N)
                bv[i] = *(const float4*)&Bw[(size_t)(n0 + row) * K + kc + kq * 4];
            else
                bv[i] = make_float4(0.f, 0.f, 0.f, 0.f);
        }
    };
    // --- store staged registers to smem buffer (with tf32 round) ---
    auto store_tile = [&](int buf) {
        #pragma unroll
        for (int i = 0; i < 4; i++) {
            int idx = tid + i * 256;
            int row = idx >> 3, kq = idx & 7;
            uint4 u;
            u.x = f2tf32(av[i].x); u.y = f2tf32(av[i].y);
            u.z = f2tf32(av[i].z); u.w = f2tf32(av[i].w);
            *(uint4*)&Abuf[buf][row * GPAD + kq * 4] = u;
            uint4 v;
            v.x = f2tf32(bv[i].x); v.y = f2tf32(bv[i].y);
            v.z = f2tf32(bv[i].z); v.w = f2tf32(bv[i].w);
            *(uint4*)&Bbuf[buf][row * GPAD + kq * 4] = v;
        }
    };

    int nk = K / GKT;
    load_regs(0);
    store_tile(0);
    __syncthreads();
    int buf = 0;

    for (int kt = 0; kt < nk; kt++) {
        bool more = (kt + 1 < nk);
        if (more) load_regs(kt + 1);

        const uint32_t* As = Abuf[buf];
        const uint32_t* Bs = Bbuf[buf];
        #pragma unroll
        for (int s = 0; s < 4; s++) {
            int k8 = s * 8;
            uint32_t a[4][4], b[4][2];
            #pragma unroll
            for (int mi = 0; mi < 4; mi++) {
                int r0 = (mb + mi * 16 + grp) * GPAD;
                a[mi][0] = As[r0 + k8 + tig];
                a[mi][1] = As[r0 + 8 * GPAD + k8 + tig];
                a[mi][2] = As[r0 + k8 + tig + 4];
                a[mi][3] = As[r0 + 8 * GPAD + k8 + tig + 4];
            }
            #pragma unroll
            for (int ni = 0; ni < 4; ni++) {
                int rn = (nb2 + ni * 8 + grp) * GPAD;
                b[ni][0] = Bs[rn + k8 + tig];
                b[ni][1] = Bs[rn + k8 + tig + 4];
            }
            #pragma unroll
            for (int mi = 0; mi < 4; mi++)
                #pragma unroll
                for (int ni = 0; ni < 4; ni++) {
                    asm volatile(
                        "mma.sync.aligned.m16n8k8.row.col.f32.tf32.tf32.f32 "
                        "{%0,%1,%2,%3}, {%4,%5,%6,%7}, {%8,%9}, {%0,%1,%2,%3};"
                        : "+f"(c[mi][ni][0]), "+f"(c[mi][ni][1]),
                          "+f"(c[mi][ni][2]), "+f"(c[mi][ni][3])
                        : "r"(a[mi][0]), "r"(a[mi][1]), "r"(a[mi][2]), "r"(a[mi][3]),
                          "r"(b[ni][0]), "r"(b[ni][1]));
                }
        }

        if (more) {
            store_tile(buf ^ 1);
            __syncthreads();
            buf ^= 1;
        }
    }

    // epilogue
    #pragma unroll
    for (int mi = 0; mi < 4; mi++) {
        int row = m0 + mb + mi * 16 + grp;
        #pragma unroll
        for (int ni = 0; ni < 4; ni++) {
            int col = n0 + nb2 + ni * 8 + tig * 2;
            if (col < N) {
                float v0 = c[mi][ni][0], v1 = c[mi][ni][1];
                float v2 = c[mi][ni][2], v3 = c[mi][ni][3];
                if (R) {
                    float2 r0 = *(const float2*)&R[(size_t)row * ldc + col];
                    float2 r1 = *(const float2*)&R[(size_t)(row + 8) * ldc + col];
                    v0 += r0.x; v1 += r0.y; v2 += r1.x; v3 += r1.y;
                }
                *(float2*)&C[(size_t)row * ldc + col]       = make_float2(v0, v1);
                *(float2*)&C[(size_t)(row + 8) * ldc + col] = make_float2(v2, v3);
            }
        }
    }
}

// ---------------- K3: conv1d + silu + softplus(dt) + decay ----------------
__global__ void k_conv(int dir,
                       const float* __restrict__ conv_w, const float* __restrict__ conv_b,
                       const float* __restrict__ dt_bias, const float* __restrict__ A_log)
{
    int token = blockIdx.x;
    int b = token >> 10, s = token & 1023;
    const float* zx = g_zx[dir];
    float* out = g_conv[dir] + (size_t)token * CD;

    for (int c = threadIdx.x; c < CD; c += blockDim.x) {
        float acc = conv_b[c];
        const float* w = conv_w + c * 4;
        #pragma unroll
        for (int k = 0; k < 4; k++) {
            int sp = (dir == 0) ? (s - 3 + k) : (s + 3 - k);
            if (sp >= 0 && sp < LL)
                acc = fmaf(zx[(size_t)(b * LL + sp) * DIP + DI + c], w[k], acc);
        }
        out[c] = acc / (1.f + __expf(-acc));
    }
    if (threadIdx.x < NH) {
        int h = threadIdx.x;
        float v = zx[(size_t)token * DIP + DI + CD + h] + dt_bias[h];
        float dt = (v > 20.f) ? v : log1pf(expf(v));
        g_dt[dir][token * NH + h]  = dt;
        g_dec[dir][token * NH + h] = expf(-dt * expf(A_log[h]));
    }
}

// ---------------- K4: selective scan (chunked, latency-hidden) ----------------
// block = (dir,b,h); 256 threads: p = tid>>2, 16-wide n slice = tid&3.
// 8 timesteps per sync epoch; next chunk prefetched into regs during compute.
#define TC 8
__global__ void __launch_bounds__(256, 1) k_scan(const float* __restrict__ fD,
                                                 const float* __restrict__ bD)
{
    int blk = blockIdx.x;
    int dir = blk >> 6;
    int b   = (blk >> 4) & 3;
    int h   = blk & 15;
    const float* conv = g_conv[dir];
    const float* dts  = g_dt[dir];
    const float* decs = g_dec[dir];
    float* y = g_y[dir];
    float Dh = (dir ? bD : fD)[h];

    int tid = threadIdx.x;
    int p  = tid >> 2;
    int nb = (tid & 3) * 16;

    int c = -1;
    if (tid < 64)       c = h * 64 + tid;
    else if (tid < 128) c = DI + (tid - 64);
    else if (tid < 192) c = DI + 64 + (tid - 128);

    float st[16];
    #pragma unroll
    for (int j = 0; j < 16; j++) st[j] = 0.f;

    __shared__ float sm[TC][200];  // [x 0..63 | B 64..127 | C 128..191 | dec@192 | dt@193]
    float v[TC];

    auto load_chunk = [&](int ch) {
        #pragma unroll
        for (int tt = 0; tt < TC; tt++) {
            int t = ch * TC + tt;
            int s = dir ? (LL - 1 - t) : t;
            int token = b * LL + s;
            if (tid < 192)        v[tt] = conv[(size_t)token * CD + c];
            else if (tid == 192)  v[tt] = decs[token * NH + h];
            else if (tid == 193)  v[tt] = dts[token * NH + h];
        }
    };

    load_chunk(0);
    const int NCH = LL / TC;
    for (int ch = 0; ch < NCH; ch++) {
        __syncthreads();
        if (tid < 194) {
            #pragma unroll
            for (int tt = 0; tt < TC; tt++) sm[tt][tid] = v[tt];
        }
        __syncthreads();
        if (ch + 1 < NCH) load_chunk(ch + 1);

        #pragma unroll
        for (int tt = 0; tt < TC; tt++) {
            int t = ch * TC + tt;
            int s = dir ? (LL - 1 - t) : t;
            int token = b * LL + s;
            float dec = sm[tt][192];
            float dtx = sm[tt][193] * sm[tt][p];
            float acc = 0.f;
            #pragma unroll
            for (int j = 0; j < 16; j++) {
                st[j] = fmaf(st[j], dec, dtx * sm[tt][64 + nb + j]);
                acc = fmaf(st[j], sm[tt][128 + nb + j], acc);
            }
            acc += __shfl_xor_sync(0xffffffffu, acc, 1);
            acc += __shfl_xor_sync(0xffffffffu, acc, 2);
            if ((tid & 3) == 0)
                y[(size_t)token * DI + h * 64 + p] = acc + Dh * sm[tt][p];
        }
    }
}

// ---------------- K5: gating (y * silu(z)) + rmsnorm ----------------
__global__ void k_gatenorm(const float* __restrict__ f_gw, const float* __restrict__ b_gw)
{
    int row = blockIdx.x;
    int dir = blockIdx.y;
    const float* gw = dir ? b_gw : f_gw;
    const float* z = g_zx[dir] + (size_t)row * DIP;
    float* y = g_y[dir] + (size_t)row * DI;
    int tid = threadIdx.x;

    float g[4];
    float ss = 0.f;
    #pragma unroll
    for (int i = 0; i < 4; i++) {
        int cidx = tid + i * 256;
        float zv = z[cidx];
        float gv = y[cidx] * (zv / (1.f + __expf(-zv)));
        g[i] = gv;
        ss += gv * gv;
    }
    __shared__ float red[8];
    float tot = block_reduce_sum_256(ss, red);
    float scale = rsqrtf(tot / (float)DI + 1e-5f);
    #pragma unroll
    for (int i = 0; i < 4; i++) {
        int cidx = tid + i * 256;
        y[cidx] = g[i] * scale * gw[cidx];
    }
}

// ---------------- launcher ----------------
extern "C" void kernel_launch(void* const* d_in, const int* in_sizes, int n_in,
                              void* d_out, int out_size)
{
    (void)in_sizes; (void)n_in; (void)out_size;
    const float* x       = (const float*)d_in[0];
    const float* norm_w  = (const float*)d_in[1];
    const float* in_w[2]   = {(const float*)d_in[2],  (const float*)d_in[10]};
    const float* conv_w[2] = {(const float*)d_in[3],  (const float*)d_in[11]};
    const float* conv_b[2] = {(const float*)d_in[4],  (const float*)d_in[12]};
    const float* dt_b[2]   = {(const float*)d_in[5],  (const float*)d_in[13]};
    const float* A_log[2]  = {(const float*)d_in[6],  (const float*)d_in[14]};
    const float* Dp[2]     = {(const float*)d_in[7],  (const float*)d_in[15]};
    const float* gnorm[2]  = {(const float*)d_in[8],  (const float*)d_in[16]};
    const float* out_w[2]  = {(const float*)d_in[9],  (const float*)d_in[17]};
    const float* proj_w    = (const float*)d_in[18];
    float* out = (float*)d_out;

    float *p_h, *p_zx, *p_y, *p_cat;
    cudaGetSymbolAddress((void**)&p_h,   g_h);
    cudaGetSymbolAddress((void**)&p_zx,  g_zx);
    cudaGetSymbolAddress((void**)&p_y,   g_y);
    cudaGetSymbolAddress((void**)&p_cat, g_cat);

    cudaFuncSetAttribute(k_gemm_tf32,
                         cudaFuncAttributeMaxDynamicSharedMemorySize, GEMM_SMEM);

    // 1. input rmsnorm
    k_rmsnorm_in<<<MM, 256>>>(x, norm_w);

    // 2. in_proj (both dirs): 4096 x 2192, K=512
    {
        dim3 grid((DIP + 127) / 128, MM / 128);
        for (int d = 0; d < 2; d++)
            k_gemm_tf32<<<grid, 256, GEMM_SMEM>>>(p_h, in_w[d],
                                                  p_zx + (size_t)d * MM * DIP, nullptr,
                                                  DIP, DM, DIP);
    }

    // 3. conv + activations
    for (int d = 0; d < 2; d++)
        k_conv<<<MM, 256>>>(d, conv_w[d], conv_b[d], dt_b[d], A_log[d]);

    // 4. selective scan
    k_scan<<<128, 256>>>(Dp[0], Dp[1]);

    // 5. gate + rmsnorm
    {
        dim3 grid(MM, 2);
        k_gatenorm<<<grid, 256>>>(gnorm[0], gnorm[1]);
    }

    // 6. out_proj: 4096 x 512, K=1024
    {
        dim3 grid((DM + 127) / 128, MM / 128);
        for (int d = 0; d < 2; d++)
            k_gemm_tf32<<<grid, 256, GEMM_SMEM>>>(p_y + (size_t)d * MM * DI, out_w[d],
                                                  p_cat + (size_t)d * DM, nullptr,
                                                  DM, DI, 2 * DM);
    }

    // 7. final: out = x + cat @ proj_w^T  (4096 x 512, K=1024)
    {
        dim3 grid((DM + 127) / 128, MM / 128);
        k_gemm_tf32<<<grid, 256, GEMM_SMEM>>>(p_cat, proj_w, out, x, DM, 2 * DM, DM);
    }
}

// round 4
// speedup vs baseline: 2.5072x; 1.0000x over previous
#include <cuda_runtime.h>
#include <math.h>
#include <stdint.h>

// ---------------- problem constants ----------------
#define BB   4
#define LL   1024
#define DM   512        // d_model
#define DI   1024       // d_inner
#define DS   64         // d_state
#define NH   16         // heads
#define HD   64         // headdim
#define CD   1152       // conv dim = DI + 2*DS
#define DIP  2192       // in_proj out = 2*DI + 2*DS + NH
#define MM   (BB*LL)    // 4096 tokens

// ---------------- scratch (static device memory; no allocs) ----------------
__device__ __align__(128) float g_h   [MM*DM];
__device__ __align__(128) float g_zx  [2][MM*DIP];
__device__ __align__(128) float g_conv[2][MM*CD];
__device__ __align__(128) float g_dt  [2][MM*NH];
__device__ __align__(128) float g_dec [2][MM*NH];
__device__ __align__(128) float g_y   [2][MM*DI];
__device__ __align__(128) float g_cat [MM*2*DM];

// ---------------- helpers ----------------
__device__ __forceinline__ float block_reduce_sum_256(float v, float* red) {
    int tid = threadIdx.x;
    #pragma unroll
    for (int o = 16; o; o >>= 1) v += __shfl_xor_sync(0xffffffffu, v, o);
    if ((tid & 31) == 0) red[tid >> 5] = v;
    __syncthreads();
    float t = (tid < 8) ? red[tid] : 0.f;
    if (tid < 32) {
        #pragma unroll
        for (int o = 4; o; o >>= 1) t += __shfl_xor_sync(0xffffffffu, t, o);
        if (tid == 0) red[0] = t;
    }
    __syncthreads();
    return red[0];
}

__device__ __forceinline__ uint32_t f2tf32(float f) {
    uint32_t u;
    asm("cvt.rna.tf32.f32 %0, %1;" : "=r"(u) : "f"(f));
    return u;
}

// ---------------- K1: input rmsnorm ----------------
__global__ void k_rmsnorm_in(const float* __restrict__ x, const float* __restrict__ w) {
    int row = blockIdx.x;
    int tid = threadIdx.x;
    const float* xr = x + (size_t)row * DM;
    float v0 = xr[tid], v1 = xr[tid + 256];
    __shared__ float red[8];
    float ss = block_reduce_sum_256(v0 * v0 + v1 * v1, red);
    float scale = rsqrtf(ss / (float)DM + 1e-5f);
    g_h[(size_t)row * DM + tid]       = v0 * scale * w[tid];
    g_h[(size_t)row * DM + tid + 256] = v1 * scale * w[tid + 256];
}

// ---------------- K2: tf32 tensor-core NT GEMM ----------------
// C[M,N] = A[M,K] @ B[N,K]^T (+R).  Block tile 128x128, K-tile 32.
// 8 warps, each computes 64(m) x 32(n) via m16n8k8 tf32 mma.sync.
// SMEM rows padded to 36 u32 -> fragment LDS conflict-free.
#define GKT   32
#define GPAD  36
#define TILEW (128*GPAD)          // u32 per (matrix, buffer)
#define GEMM_SMEM (4*TILEW*4)     // bytes: A0,A1,B0,B1

__global__ void __launch_bounds__(256) k_gemm_tf32(
    const float* __restrict__ A, const float* __restrict__ Bw,
    float* __restrict__ C, const float* __restrict__ R,
    int N, int K, int ldc)
{
    extern __shared__ uint32_t smem[];
    uint32_t* Abuf[2] = { smem,            smem + TILEW };
    uint32_t* Bbuf[2] = { smem + 2*TILEW,  smem + 3*TILEW };

    int tid  = threadIdx.x;
    int warp = tid >> 5, lane = tid & 31;
    int grp  = lane >> 2, tig = lane & 3;
    int m0 = blockIdx.y * 128;
    int n0 = blockIdx.x * 128;
    int mb  = (warp & 1) * 64;     // warp m-offset
    int nb2 = (warp >> 1) * 32;    // warp n-offset

    float c[4][4][4];
    #pragma unroll
    for (int mi = 0; mi < 4; mi++)
        #pragma unroll
        for (int ni = 0; ni < 4; ni++)
            #pragma unroll
            for (int q = 0; q < 4; q++) c[mi][ni][q] = 0.f;

    float4 av[4], bv[4];

    // --- stage tile kt into registers ---
    auto load_regs = [&](int kt) {
        int kc = kt * GKT;
        #pragma unroll
        for (int i = 0; i < 4; i++) {
            int idx = tid + i * 256;
            int row = idx >> 3, kq = idx & 7;
            av[i] = *(const float4*)&A[(size_t)(m0 + row) * K + kc + kq * 4];
        }
        #pragma unroll
        for (int i = 0; i < 4; i++) {
            int idx = tid + i * 256;
            int row = idx >> 3, kq = idx & 7;
            if (n0 + row < N)
                bv[i] = *(const float4*)&Bw[(size_t)(n0 + row) * K + kc + kq * 4];
            else
                bv[i] = make_float4(0.f, 0.f, 0.f, 0.f);
        }
    };
    // --- store staged registers to smem buffer (with tf32 round) ---
    auto store_tile = [&](int buf) {
        #pragma unroll
        for (int i = 0; i < 4; i++) {
            int idx = tid + i * 256;
            int row = idx >> 3, kq = idx & 7;
            uint4 u;
            u.x = f2tf32(av[i].x); u.y = f2tf32(av[i].y);
            u.z = f2tf32(av[i].z); u.w = f2tf32(av[i].w);
            *(uint4*)&Abuf[buf][row * GPAD + kq * 4] = u;
            uint4 v;
            v.x = f2tf32(bv[i].x); v.y = f2tf32(bv[i].y);
            v.z = f2tf32(bv[i].z); v.w = f2tf32(bv[i].w);
            *(uint4*)&Bbuf[buf][row * GPAD + kq * 4] = v;
        }
    };

    int nk = K / GKT;
    load_regs(0);
    store_tile(0);
    __syncthreads();
    int buf = 0;

    for (int kt = 0; kt < nk; kt++) {
        bool more = (kt + 1 < nk);
        if (more) load_regs(kt + 1);

        const uint32_t* As = Abuf[buf];
        const uint32_t* Bs = Bbuf[buf];
        #pragma unroll
        for (int s = 0; s < 4; s++) {
            int k8 = s * 8;
            uint32_t a[4][4], b[4][2];
            #pragma unroll
            for (int mi = 0; mi < 4; mi++) {
                int r0 = (mb + mi * 16 + grp) * GPAD;
                a[mi][0] = As[r0 + k8 + tig];
                a[mi][1] = As[r0 + 8 * GPAD + k8 + tig];
                a[mi][2] = As[r0 + k8 + tig + 4];
                a[mi][3] = As[r0 + 8 * GPAD + k8 + tig + 4];
            }
            #pragma unroll
            for (int ni = 0; ni < 4; ni++) {
                int rn = (nb2 + ni * 8 + grp) * GPAD;
                b[ni][0] = Bs[rn + k8 + tig];
                b[ni][1] = Bs[rn + k8 + tig + 4];
            }
            #pragma unroll
            for (int mi = 0; mi < 4; mi++)
                #pragma unroll
                for (int ni = 0; ni < 4; ni++) {
                    asm volatile(
                        "mma.sync.aligned.m16n8k8.row.col.f32.tf32.tf32.f32 "
                        "{%0,%1,%2,%3}, {%4,%5,%6,%7}, {%8,%9}, {%0,%1,%2,%3};"
                        : "+f"(c[mi][ni][0]), "+f"(c[mi][ni][1]),
                          "+f"(c[mi][ni][2]), "+f"(c[mi][ni][3])
                        : "r"(a[mi][0]), "r"(a[mi][1]), "r"(a[mi][2]), "r"(a[mi][3]),
                          "r"(b[ni][0]), "r"(b[ni][1]));
                }
        }

        if (more) {
            store_tile(buf ^ 1);
            __syncthreads();
            buf ^= 1;
        }
    }

    // epilogue
    #pragma unroll
    for (int mi = 0; mi < 4; mi++) {
        int row = m0 + mb + mi * 16 + grp;
        #pragma unroll
        for (int ni = 0; ni < 4; ni++) {
            int col = n0 + nb2 + ni * 8 + tig * 2;
            if (col < N) {
                float v0 = c[mi][ni][0], v1 = c[mi][ni][1];
                float v2 = c[mi][ni][2], v3 = c[mi][ni][3];
                if (R) {
                    float2 r0 = *(const float2*)&R[(size_t)row * ldc + col];
                    float2 r1 = *(const float2*)&R[(size_t)(row + 8) * ldc + col];
                    v0 += r0.x; v1 += r0.y; v2 += r1.x; v3 += r1.y;
                }
                *(float2*)&C[(size_t)row * ldc + col]       = make_float2(v0, v1);
                *(float2*)&C[(size_t)(row + 8) * ldc + col] = make_float2(v2, v3);
            }
        }
    }
}

// ---------------- K3: conv1d + silu + softplus(dt) + decay ----------------
__global__ void k_conv(int dir,
                       const float* __restrict__ conv_w, const float* __restrict__ conv_b,
                       const float* __restrict__ dt_bias, const float* __restrict__ A_log)
{
    int token = blockIdx.x;
    int b = token >> 10, s = token & 1023;
    const float* zx = g_zx[dir];
    float* out = g_conv[dir] + (size_t)token * CD;

    for (int c = threadIdx.x; c < CD; c += blockDim.x) {
        float acc = conv_b[c];
        const float* w = conv_w + c * 4;
        #pragma unroll
        for (int k = 0; k < 4; k++) {
            int sp = (dir == 0) ? (s - 3 + k) : (s + 3 - k);
            if (sp >= 0 && sp < LL)
                acc = fmaf(zx[(size_t)(b * LL + sp) * DIP + DI + c], w[k], acc);
        }
        out[c] = acc / (1.f + __expf(-acc));
    }
    if (threadIdx.x < NH) {
        int h = threadIdx.x;
        float v = zx[(size_t)token * DIP + DI + CD + h] + dt_bias[h];
        float dt = (v > 20.f) ? v : log1pf(expf(v));
        g_dt[dir][token * NH + h]  = dt;
        g_dec[dir][token * NH + h] = expf(-dt * expf(A_log[h]));
    }
}

// ---------------- K4: selective scan (chunked, latency-hidden) ----------------
// block = (dir,b,h); 256 threads: p = tid>>2, 16-wide n slice = tid&3.
// 8 timesteps per sync epoch; next chunk prefetched into regs during compute.
#define TC 8
__global__ void __launch_bounds__(256, 1) k_scan(const float* __restrict__ fD,
                                                 const float* __restrict__ bD)
{
    int blk = blockIdx.x;
    int dir = blk >> 6;
    int b   = (blk >> 4) & 3;
    int h   = blk & 15;
    const float* conv = g_conv[dir];
    const float* dts  = g_dt[dir];
    const float* decs = g_dec[dir];
    float* y = g_y[dir];
    float Dh = (dir ? bD : fD)[h];

    int tid = threadIdx.x;
    int p  = tid >> 2;
    int nb = (tid & 3) * 16;

    int c = -1;
    if (tid < 64)       c = h * 64 + tid;
    else if (tid < 128) c = DI + (tid - 64);
    else if (tid < 192) c = DI + 64 + (tid - 128);

    float st[16];
    #pragma unroll
    for (int j = 0; j < 16; j++) st[j] = 0.f;

    __shared__ float sm[TC][200];  // [x 0..63 | B 64..127 | C 128..191 | dec@192 | dt@193]
    float v[TC];

    auto load_chunk = [&](int ch) {
        #pragma unroll
        for (int tt = 0; tt < TC; tt++) {
            int t = ch * TC + tt;
            int s = dir ? (LL - 1 - t) : t;
            int token = b * LL + s;
            if (tid < 192)        v[tt] = conv[(size_t)token * CD + c];
            else if (tid == 192)  v[tt] = decs[token * NH + h];
            else if (tid == 193)  v[tt] = dts[token * NH + h];
        }
    };

    load_chunk(0);
    const int NCH = LL / TC;
    for (int ch = 0; ch < NCH; ch++) {
        __syncthreads();
        if (tid < 194) {
            #pragma unroll
            for (int tt = 0; tt < TC; tt++) sm[tt][tid] = v[tt];
        }
        __syncthreads();
        if (ch + 1 < NCH) load_chunk(ch + 1);

        #pragma unroll
        for (int tt = 0; tt < TC; tt++) {
            int t = ch * TC + tt;
            int s = dir ? (LL - 1 - t) : t;
            int token = b * LL + s;
            float dec = sm[tt][192];
            float dtx = sm[tt][193] * sm[tt][p];
            float acc = 0.f;
            #pragma unroll
            for (int j = 0; j < 16; j++) {
                st[j] = fmaf(st[j], dec, dtx * sm[tt][64 + nb + j]);
                acc = fmaf(st[j], sm[tt][128 + nb + j], acc);
            }
            acc += __shfl_xor_sync(0xffffffffu, acc, 1);
            acc += __shfl_xor_sync(0xffffffffu, acc, 2);
            if ((tid & 3) == 0)
                y[(size_t)token * DI + h * 64 + p] = acc + Dh * sm[tt][p];
        }
    }
}

// ---------------- K5: gating (y * silu(z)) + rmsnorm ----------------
__global__ void k_gatenorm(const float* __restrict__ f_gw, const float* __restrict__ b_gw)
{
    int row = blockIdx.x;
    int dir = blockIdx.y;
    const float* gw = dir ? b_gw : f_gw;
    const float* z = g_zx[dir] + (size_t)row * DIP;
    float* y = g_y[dir] + (size_t)row * DI;
    int tid = threadIdx.x;

    float g[4];
    float ss = 0.f;
    #pragma unroll
    for (int i = 0; i < 4; i++) {
        int cidx = tid + i * 256;
        float zv = z[cidx];
        float gv = y[cidx] * (zv / (1.f + __expf(-zv)));
        g[i] = gv;
        ss += gv * gv;
    }
    __shared__ float red[8];
    float tot = block_reduce_sum_256(ss, red);
    float scale = rsqrtf(tot / (float)DI + 1e-5f);
    #pragma unroll
    for (int i = 0; i < 4; i++) {
        int cidx = tid + i * 256;
        y[cidx] = g[i] * scale * gw[cidx];
    }
}

// ---------------- launcher ----------------
extern "C" void kernel_launch(void* const* d_in, const int* in_sizes, int n_in,
                              void* d_out, int out_size)
{
    (void)in_sizes; (void)n_in; (void)out_size;
    const float* x       = (const float*)d_in[0];
    const float* norm_w  = (const float*)d_in[1];
    const float* in_w[2]   = {(const float*)d_in[2],  (const float*)d_in[10]};
    const float* conv_w[2] = {(const float*)d_in[3],  (const float*)d_in[11]};
    const float* conv_b[2] = {(const float*)d_in[4],  (const float*)d_in[12]};
    const float* dt_b[2]   = {(const float*)d_in[5],  (const float*)d_in[13]};
    const float* A_log[2]  = {(const float*)d_in[6],  (const float*)d_in[14]};
    const float* Dp[2]     = {(const float*)d_in[7],  (const float*)d_in[15]};
    const float* gnorm[2]  = {(const float*)d_in[8],  (const float*)d_in[16]};
    const float* out_w[2]  = {(const float*)d_in[9],  (const float*)d_in[17]};
    const float* proj_w    = (const float*)d_in[18];
    float* out = (float*)d_out;

    float *p_h, *p_zx, *p_y, *p_cat;
    cudaGetSymbolAddress((void**)&p_h,   g_h);
    cudaGetSymbolAddress((void**)&p_zx,  g_zx);
    cudaGetSymbolAddress((void**)&p_y,   g_y);
    cudaGetSymbolAddress((void**)&p_cat, g_cat);

    cudaFuncSetAttribute(k_gemm_tf32,
                         cudaFuncAttributeMaxDynamicSharedMemorySize, GEMM_SMEM);

    // 1. input rmsnorm
    k_rmsnorm_in<<<MM, 256>>>(x, norm_w);

    // 2. in_proj (both dirs): 4096 x 2192, K=512
    {
        dim3 grid((DIP + 127) / 128, MM / 128);
        for (int d = 0; d < 2; d++)
            k_gemm_tf32<<<grid, 256, GEMM_SMEM>>>(p_h, in_w[d],
                                                  p_zx + (size_t)d * MM * DIP, nullptr,
                                                  DIP, DM, DIP);
    }

    // 3. conv + activations
    for (int d = 0; d < 2; d++)
        k_conv<<<MM, 256>>>(d, conv_w[d], conv_b[d], dt_b[d], A_log[d]);

    // 4. selective scan
    k_scan<<<128, 256>>>(Dp[0], Dp[1]);

    // 5. gate + rmsnorm
    {
        dim3 grid(MM, 2);
        k_gatenorm<<<grid, 256>>>(gnorm[0], gnorm[1]);
    }

    // 6. out_proj: 4096 x 512, K=1024
    {
        dim3 grid((DM + 127) / 128, MM / 128);
        for (int d = 0; d < 2; d++)
            k_gemm_tf32<<<grid, 256, GEMM_SMEM>>>(p_y + (size_t)d * MM * DI, out_w[d],
                                                  p_cat + (size_t)d * DM, nullptr,
                                                  DM, DI, 2 * DM);
    }

    // 7. final: out = x + cat @ proj_w^T  (4096 x 512, K=1024)
    {
        dim3 grid((DM + 127) / 128, MM / 128);
        k_gemm_tf32<<<grid, 256, GEMM_SMEM>>>(p_cat, proj_w, out, x, DM, 2 * DM, DM);
    }
}

// round 6
// speedup vs baseline: 3.1694x; 1.2641x over previous
#include <cuda_runtime.h>
#include <math.h>
#include <stdint.h>

#define BB   4
#define LL   1024
#define DM   512
#define DI   1024
#define DS   64
#define NH   16
#define CD   1152
#define DIP  2192
#define MM   (BB*LL)

#define NW_IN   (DIP*DM)
#define NW_OUT  (DM*DI)
#define W_IN0   0
#define W_OUT0  (2*NW_IN)
#define W_PROJ  (2*NW_IN + 2*NW_OUT)
#define W_TOT   (W_PROJ + DM*2*DM)

__device__ __align__(128) float g_h   [MM*DM];
__device__ __align__(128) float g_zx  [2][MM*DIP];
__device__ __align__(128) float g_conv[2][MM*CD];
__device__ __align__(128) float g_dt  [2][MM*NH];
__device__ __align__(128) float g_dec [2][MM*NH];
__device__ __align__(128) float g_y   [2][MM*DI];
__device__ __align__(128) float g_cat [MM*2*DM];
__device__ __align__(128) float g_w   [W_TOT];

// ---------------- helpers ----------------
__device__ __forceinline__ uint32_t cvta_s(const void* p){
    uint32_t a;
    asm("{ .reg .u64 t; cvta.to.shared.u64 t, %1; cvt.u32.u64 %0, t; }":"=r"(a):"l"(p));
    return a;
}
__device__ __forceinline__ void cp16(uint32_t dst, const void* src, int sz){
    asm volatile("{ .reg .u64 g; cvta.to.global.u64 g, %1;\n\t"
                 "cp.async.cg.shared.global [%0], [g], 16, %2; }"
                 :: "r"(dst), "l"(src), "r"(sz) : "memory");
}
__device__ __forceinline__ float rna_tf32(float f){
    uint32_t u; asm("cvt.rna.tf32.f32 %0, %1;" : "=r"(u) : "f"(f));
    return __uint_as_float(u);
}
__device__ __forceinline__ uint64_t pk2(float a, float b){
    uint64_t r; asm("mov.b64 %0, {%1,%2};" : "=l"(r) : "f"(a), "f"(b)); return r;
}
__device__ __forceinline__ uint64_t ffma2(uint64_t a, uint64_t b, uint64_t c){
    uint64_t d; asm("fma.rn.f32x2 %0, %1, %2, %3;" : "=l"(d) : "l"(a), "l"(b), "l"(c)); return d;
}
__device__ __forceinline__ uint64_t mul2(uint64_t a, uint64_t b){
    uint64_t d; asm("mul.rn.f32x2 %0, %1, %2;" : "=l"(d) : "l"(a), "l"(b)); return d;
}

__device__ __forceinline__ float block_reduce_sum_256(float v, float* red) {
    int tid = threadIdx.x;
    #pragma unroll
    for (int o = 16; o; o >>= 1) v += __shfl_xor_sync(0xffffffffu, v, o);
    if ((tid & 31) == 0) red[tid >> 5] = v;
    __syncthreads();
    float t = (tid < 8) ? red[tid] : 0.f;
    if (tid < 32) {
        #pragma unroll
        for (int o = 4; o; o >>= 1) t += __shfl_xor_sync(0xffffffffu, t, o);
        if (tid == 0) red[0] = t;
    }
    __syncthreads();
    return red[0];
}

// ---------------- K0: round all weights to tf32 into g_w ----------------
__global__ void k_prep(const float* __restrict__ iw0, const float* __restrict__ iw1,
                       const float* __restrict__ ow0, const float* __restrict__ ow1,
                       const float* __restrict__ pw)
{
    long long i = (long long)blockIdx.x * blockDim.x + threadIdx.x;
    if (i >= W_TOT) return;
    float v;
    if      (i < NW_IN)              v = iw0[i];
    else if (i < 2*NW_IN)            v = iw1[i - NW_IN];
    else if (i < 2*NW_IN + NW_OUT)   v = ow0[i - 2*NW_IN];
    else if (i < W_PROJ)             v = ow1[i - 2*NW_IN - NW_OUT];
    else                             v = pw [i - W_PROJ];
    g_w[i] = rna_tf32(v);
}

// ---------------- K1: input rmsnorm (out pre-rounded tf32) ----------------
__global__ void k_rmsnorm_in(const float* __restrict__ x, const float* __restrict__ w) {
    int row = blockIdx.x, tid = threadIdx.x;
    const float* xr = x + (size_t)row * DM;
    float v0 = xr[tid], v1 = xr[tid + 256];
    __shared__ float red[8];
    float ss = block_reduce_sum_256(v0 * v0 + v1 * v1, red);
    float scale = rsqrtf(ss / (float)DM + 1e-5f);
    g_h[(size_t)row * DM + tid]       = rna_tf32(v0 * scale * w[tid]);
    g_h[(size_t)row * DM + tid + 256] = rna_tf32(v1 * scale * w[tid + 256]);
}

// ---------------- K2: tf32 mma.sync NT GEMM, cp.async 3-stage pipeline --------
// C[M,N] = A[M,K] @ B[N,K]^T (+R). CTA tile 128x128, K-tile 32.
// Data pre-rounded to tf32 at producers -> raw cp.async, no in-kernel cvt.
#define ST     3
#define BK     32
#define GPAD   36
#define STAGE_W (128*GPAD)                 // floats per matrix per stage
#define GEMM_SMEM (ST*2*STAGE_W*4)         // 110592 bytes

__global__ void __launch_bounds__(256, 2) k_gemm(
    const float* __restrict__ A0, long long sA,
    const float* __restrict__ B0, long long sB,
    float* __restrict__ C0, long long sC,
    const float* __restrict__ R,
    int N, int K, int ldc, int round_c)
{
    extern __shared__ float smf[];
    const float* A  = A0 + (size_t)blockIdx.z * sA;
    const float* Bw = B0 + (size_t)blockIdx.z * sB;
    float*       C  = C0 + (size_t)blockIdx.z * sC;

    uint32_t sbase = cvta_s(smf);
    int tid = threadIdx.x, warp = tid >> 5, lane = tid & 31;
    int grp = lane >> 2, tig = lane & 3;
    int m0 = blockIdx.y * 128, n0 = blockIdx.x * 128;
    int mb = (warp & 1) * 64, nb2 = (warp >> 1) * 32;

    float c[4][4][4];
    #pragma unroll
    for (int mi = 0; mi < 4; mi++)
        #pragma unroll
        for (int ni = 0; ni < 4; ni++)
            #pragma unroll
            for (int q = 0; q < 4; q++) c[mi][ni][q] = 0.f;

    const int nk = K / BK;

    auto prefetch = [&](int kt){
        int st = kt % ST;
        uint32_t ab = sbase + (uint32_t)(st * 2 * STAGE_W) * 4;
        uint32_t bb = ab + STAGE_W * 4;
        int kc = kt * BK;
        #pragma unroll
        for (int i = 0; i < 4; i++) {
            int id = tid + i * 256, r = id >> 3, c8 = id & 7;
            uint32_t off = (uint32_t)(r * GPAD + c8 * 4) * 4;
            cp16(ab + off, &A[(size_t)(m0 + r) * K + kc + c8 * 4], 16);
            int nr = n0 + r;
            cp16(bb + off, &Bw[(size_t)(nr < N ? nr : 0) * K + kc + c8 * 4],
                 nr < N ? 16 : 0);
        }
        asm volatile("cp.async.commit_group;" ::: "memory");
    };

    prefetch(0); prefetch(1); prefetch(2);

    for (int kt = 0; kt < nk; kt++) {
        int allow = nk - 1 - kt; if (allow > 2) allow = 2;
        if (allow == 2)      asm volatile("cp.async.wait_group 2;" ::: "memory");
        else if (allow == 1) asm volatile("cp.async.wait_group 1;" ::: "memory");
        else                 asm volatile("cp.async.wait_group 0;" ::: "memory");
        __syncthreads();

        int st = kt % ST;
        const uint32_t* As = (const uint32_t*)(smf + st * 2 * STAGE_W);
        const uint32_t* Bs = As + STAGE_W;

        #pragma unroll
        for (int s = 0; s < 4; s++) {
            int k8 = s * 8;
            uint32_t a[4][4], b[4][2];
            #pragma unroll
            for (int mi = 0; mi < 4; mi++) {
                int r0 = (mb + mi * 16 + grp) * GPAD;
                a[mi][0] = As[r0 + k8 + tig];
                a[mi][1] = As[r0 + 8 * GPAD + k8 + tig];
                a[mi][2] = As[r0 + k8 + tig + 4];
                a[mi][3] = As[r0 + 8 * GPAD + k8 + tig + 4];
            }
            #pragma unroll
            for (int ni = 0; ni < 4; ni++) {
                int rn = (nb2 + ni * 8 + grp) * GPAD;
                b[ni][0] = Bs[rn + k8 + tig];
                b[ni][1] = Bs[rn + k8 + tig + 4];
            }
            #pragma unroll
            for (int mi = 0; mi < 4; mi++)
                #pragma unroll
                for (int ni = 0; ni < 4; ni++) {
                    asm volatile(
                        "mma.sync.aligned.m16n8k8.row.col.f32.tf32.tf32.f32 "
                        "{%0,%1,%2,%3}, {%4,%5,%6,%7}, {%8,%9}, {%0,%1,%2,%3};"
                        : "+f"(c[mi][ni][0]), "+f"(c[mi][ni][1]),
                          "+f"(c[mi][ni][2]), "+f"(c[mi][ni][3])
                        : "r"(a[mi][0]), "r"(a[mi][1]), "r"(a[mi][2]), "r"(a[mi][3]),
                          "r"(b[ni][0]), "r"(b[ni][1]));
                }
        }
        __syncthreads();
        if (kt + ST < nk) prefetch(kt + ST);
    }

    // epilogue
    #pragma unroll
    for (int mi = 0; mi < 4; mi++) {
        int row = m0 + mb + mi * 16 + grp;
        #pragma unroll
        for (int ni = 0; ni < 4; ni++) {
            int col = n0 + nb2 + ni * 8 + tig * 2;
            if (col < N) {
                float v0 = c[mi][ni][0], v1 = c[mi][ni][1];
                float v2 = c[mi][ni][2], v3 = c[mi][ni][3];
                if (R) {
                    float2 r0 = *(const float2*)&R[(size_t)row * ldc + col];
                    float2 r1 = *(const float2*)&R[(size_t)(row + 8) * ldc + col];
                    v0 += r0.x; v1 += r0.y; v2 += r1.x; v3 += r1.y;
                }
                if (round_c) {
                    v0 = rna_tf32(v0); v1 = rna_tf32(v1);
                    v2 = rna_tf32(v2); v3 = rna_tf32(v3);
                }
                *(float2*)&C[(size_t)row * ldc + col]       = make_float2(v0, v1);
                *(float2*)&C[(size_t)(row + 8) * ldc + col] = make_float2(v2, v3);
            }
        }
    }
}

// ---------------- K3: conv1d + silu (float4, both dirs) + fused dt ----------------
#define SEL4(v,k) ((k)==0?(v).x:(k)==1?(v).y:(k)==2?(v).z:(v).w)
__global__ void k_conv2(const float* __restrict__ fw, const float* __restrict__ fb,
                        const float* __restrict__ bw2, const float* __restrict__ bb,
                        const float* __restrict__ fdtb, const float* __restrict__ fA,
                        const float* __restrict__ bdtb, const float* __restrict__ bA)
{
    int token = blockIdx.x, dir = blockIdx.y;
    int b = token >> 10, s = token & 1023;
    const float* w  = dir ? bw2 : fw;
    const float* cb = dir ? bb : fb;
    const float* zx = g_zx[dir];
    int c = threadIdx.x * 4;

    float4 acc = *(const float4*)&cb[c];
    float4 w0 = *(const float4*)&w[(c + 0) * 4];
    float4 w1 = *(const float4*)&w[(c + 1) * 4];
    float4 w2 = *(const float4*)&w[(c + 2) * 4];
    float4 w3 = *(const float4*)&w[(c + 3) * 4];

    #pragma unroll
    for (int k = 0; k < 4; k++) {
        int sp = dir ? (s + 3 - k) : (s - 3 + k);
        if (sp >= 0 && sp < LL) {
            float4 v = *(const float4*)&zx[(size_t)(b * LL + sp) * DIP + DI + c];
            acc.x = fmaf(v.x, SEL4(w0, k), acc.x);
            acc.y = fmaf(v.y, SEL4(w1, k), acc.y);
            acc.z = fmaf(v.z, SEL4(w2, k), acc.z);
            acc.w = fmaf(v.w, SEL4(w3, k), acc.w);
        }
    }
    float4 o;
    o.x = acc.x / (1.f + __expf(-acc.x));
    o.y = acc.y / (1.f + __expf(-acc.y));
    o.z = acc.z / (1.f + __expf(-acc.z));
    o.w = acc.w / (1.f + __expf(-acc.w));
    *(float4*)&g_conv[dir][(size_t)token * CD + c] = o;

    if (threadIdx.x < NH) {
        int h = threadIdx.x;
        float v = zx[(size_t)token * DIP + DI + CD + h] + (dir ? bdtb : fdtb)[h];
        float dt = (v > 20.f) ? v : log1pf(expf(v));
        g_dt[dir][token * NH + h]  = dt;
        g_dec[dir][token * NH + h] = expf(-dt * expf((dir ? bA : fA)[h]));
    }
}

// ---------------- K4: selective scan (f32x2 packed, chunked prefetch) ----------------
#define TC 8
__global__ void __launch_bounds__(256, 1) k_scan(const float* __restrict__ fD,
                                                 const float* __restrict__ bD)
{
    int blk = blockIdx.x;
    int dir = blk >> 6, b = (blk >> 4) & 3, h = blk & 15;
    const float* conv = g_conv[dir];
    const float* dts  = g_dt[dir];
    const float* decs = g_dec[dir];
    float* y = g_y[dir];
    float Dh = (dir ? bD : fD)[h];

    int tid = threadIdx.x;
    int p  = tid >> 2;
    int nb = (tid & 3) * 16;

    int c = -1;
    if (tid < 64)       c = h * 64 + tid;
    else if (tid < 128) c = DI + (tid - 64);
    else if (tid < 192) c = DI + 64 + (tid - 128);

    uint64_t st2[8];
    #pragma unroll
    for (int j = 0; j < 8; j++) st2[j] = 0ull;

    __shared__ __align__(16) float sm[TC][200];
    float v[TC];

    auto load_chunk = [&](int ch){
        #pragma unroll
        for (int tt = 0; tt < TC; tt++) {
            int t = ch * TC + tt;
            int s = dir ? (LL - 1 - t) : t;
            int token = b * LL + s;
            if (tid < 192)        v[tt] = conv[(size_t)token * CD + c];
            else if (tid == 192)  v[tt] = decs[token * NH + h];
            else if (tid == 193)  v[tt] = dts[token * NH + h];
        }
    };

    load_chunk(0);
    const int NCH = LL / TC;
    for (int ch = 0; ch < NCH; ch++) {
        __syncthreads();
        if (tid < 194) {
            #pragma unroll
            for (int tt = 0; tt < TC; tt++) sm[tt][tid] = v[tt];
        }
        __syncthreads();
        if (ch + 1 < NCH) load_chunk(ch + 1);

        #pragma unroll
        for (int tt = 0; tt < TC; tt++) {
            int t = ch * TC + tt;
            int s = dir ? (LL - 1 - t) : t;
            int token = b * LL + s;
            float dec = sm[tt][192], dtv = sm[tt][193], xv = sm[tt][p];
            uint64_t dec2 = pk2(dec, dec);
            uint64_t dtx2 = pk2(dtv * xv, dtv * xv);
            uint64_t acc2 = 0ull;
            #pragma unroll
            for (int q = 0; q < 4; q++) {
                ulonglong2 bq = *(const ulonglong2*)&sm[tt][64 + nb + q * 4];
                ulonglong2 cq = *(const ulonglong2*)&sm[tt][128 + nb + q * 4];
                st2[2*q]   = ffma2(st2[2*q],   dec2, mul2(dtx2, bq.x));
                st2[2*q+1] = ffma2(st2[2*q+1], dec2, mul2(dtx2, bq.y));
                acc2 = ffma2(st2[2*q],   cq.x, acc2);
                acc2 = ffma2(st2[2*q+1], cq.y, acc2);
            }
            float alo = __uint_as_float((uint32_t)acc2);
            float ahi = __uint_as_float((uint32_t)(acc2 >> 32));
            float acc = alo + ahi;
            acc += __shfl_xor_sync(0xffffffffu, acc, 1);
            acc += __shfl_xor_sync(0xffffffffu, acc, 2);
            if ((tid & 3) == 0)
                y[(size_t)token * DI + h * 64 + p] = acc + Dh * xv;
        }
    }
}

// ---------------- K5: gate (y*silu(z)) + rmsnorm (out pre-rounded tf32) ----------
__global__ void k_gatenorm(const float* __restrict__ f_gw, const float* __restrict__ b_gw)
{
    int row = blockIdx.x, dir = blockIdx.y;
    const float* gw = dir ? b_gw : f_gw;
    const float* z = g_zx[dir] + (size_t)row * DIP;
    float* y = g_y[dir] + (size_t)row * DI;
    int tid = threadIdx.x;

    float g[4];
    float ss = 0.f;
    #pragma unroll
    for (int i = 0; i < 4; i++) {
        int cidx = tid + i * 256;
        float zv = z[cidx];
        float gv = y[cidx] * (zv / (1.f + __expf(-zv)));
        g[i] = gv;
        ss += gv * gv;
    }
    __shared__ float red[8];
    float tot = block_reduce_sum_256(ss, red);
    float scale = rsqrtf(tot / (float)DI + 1e-5f);
    #pragma unroll
    for (int i = 0; i < 4; i++) {
        int cidx = tid + i * 256;
        y[cidx] = rna_tf32(g[i] * scale * gw[cidx]);
    }
}

// ---------------- launcher ----------------
extern "C" void kernel_launch(void* const* d_in, const int* in_sizes, int n_in,
                              void* d_out, int out_size)
{
    (void)in_sizes; (void)n_in; (void)out_size;
    const float* x       = (const float*)d_in[0];
    const float* norm_w  = (const float*)d_in[1];
    const float* in_w[2]   = {(const float*)d_in[2],  (const float*)d_in[10]};
    const float* conv_w[2] = {(const float*)d_in[3],  (const float*)d_in[11]};
    const float* conv_b[2] = {(const float*)d_in[4],  (const float*)d_in[12]};
    const float* dt_b[2]   = {(const float*)d_in[5],  (const float*)d_in[13]};
    const float* A_log[2]  = {(const float*)d_in[6],  (const float*)d_in[14]};
    const float* Dp[2]     = {(const float*)d_in[7],  (const float*)d_in[15]};
    const float* gnorm[2]  = {(const float*)d_in[8],  (const float*)d_in[16]};
    const float* out_w[2]  = {(const float*)d_in[9],  (const float*)d_in[17]};
    const float* proj_w    = (const float*)d_in[18];
    float* out = (float*)d_out;

    float *p_h, *p_zx, *p_y, *p_cat, *p_w;
    cudaGetSymbolAddress((void**)&p_h,   g_h);
    cudaGetSymbolAddress((void**)&p_zx,  g_zx);
    cudaGetSymbolAddress((void**)&p_y,   g_y);
    cudaGetSymbolAddress((void**)&p_cat, g_cat);
    cudaGetSymbolAddress((void**)&p_w,   g_w);

    cudaFuncSetAttribute(k_gemm,
                         cudaFuncAttributeMaxDynamicSharedMemorySize, GEMM_SMEM);

    // 0. weight prep (tf32 rna round)
    k_prep<<<(W_TOT + 255) / 256, 256>>>(in_w[0], in_w[1], out_w[0], out_w[1], proj_w);

    // 1. input rmsnorm
    k_rmsnorm_in<<<MM, 256>>>(x, norm_w);

    // 2. in_proj both dirs: 4096 x 2192, K=512
    {
        dim3 grid((DIP + 127) / 128, MM / 128, 2);
        k_gemm<<<grid, 256, GEMM_SMEM>>>(p_h, 0LL,
                                         p_w + W_IN0, (long long)NW_IN,
                                         p_zx, (long long)MM * DIP,
                                         nullptr, DIP, DM, DIP, 0);
    }

    // 3. conv + silu + dt (both dirs)
    {
        dim3 cgrid(MM, 2);
        k_conv2<<<cgrid, CD / 4>>>(conv_w[0], conv_b[0], conv_w[1], conv_b[1],
                                   dt_b[0], A_log[0], dt_b[1], A_log[1]);
    }

    // 4. selective scan
    k_scan<<<128, 256>>>(Dp[0], Dp[1]);

    // 5. gate + rmsnorm
    {
        dim3 grid(MM, 2);
        k_gatenorm<<<grid, 256>>>(gnorm[0], gnorm[1]);
    }

    // 6. out_proj both dirs: 4096 x 512, K=1024 (round output for final GEMM)
    {
        dim3 grid(DM / 128, MM / 128, 2);
        k_gemm<<<grid, 256, GEMM_SMEM>>>(p_y, (long long)MM * DI,
                                         p_w + W_OUT0, (long long)NW_OUT,
                                         p_cat, (long long)DM,
                                         nullptr, DM, DI, 2 * DM, 1);
    }

    // 7. final: out = x + cat @ proj_w^T  (4096 x 512, K=1024)
    {
        dim3 grid(DM / 128, MM / 128, 1);
        k_gemm<<<grid, 256, GEMM_SMEM>>>(p_cat, 0LL,
                                         p_w + W_PROJ, 0LL,
                                         out, 0LL,
                                         x, DM, 2 * DM, DM, 0);
    }
}